// round 1
// baseline (speedup 1.0000x reference)
#include <cuda_runtime.h>
#include <math.h>

// Problem constants
#define NB    64
#define CIN   8
#define LEN   16384
#define HID   64
#define LOUT  4096

// Tiling: one CTA computes 128 patches (1 halo + 127 primary) and exclusively
// writes 508 output positions (padded coords q in [508*b, 508*b+508)).
#define PB      127        // primary patches per block
#define PQ      508        // positions per block (4*PB)
#define TPATCH  128        // patches computed per block (PB + 1 halo)
#define NBLK    33         // ceil((LEN+2)/PQ)

// Shared memory layout (float offsets). Region A (h_s) overlays xtile;
// o_s overlays feats. Total 25472 floats = 101888 bytes -> 2 CTAs/SM.
#define XT_ROW   520       // xtile row stride (516 used)
#define XT_USED  516
#define HS_ROW   132       // h_s row stride (pad vs 128 to cut STS conflicts)
#define FE_OFF   8448      // feats[64][128] / o_s[128][64]
#define W1_OFF   16640     // w1t[64][68]
#define W2_OFF   20992     // w2t[64][68]
#define B1_OFF   25344
#define B2_OFF   25408
#define SMEM_FLOATS 25472

__global__ __launch_bounds__(256, 2)
void fused_conv_mlp_kernel(const float* __restrict__ x,
                           const float* __restrict__ W1,
                           const float* __restrict__ b1,
                           const float* __restrict__ W2,
                           const float* __restrict__ b2,
                           float* __restrict__ out)
{
    extern __shared__ float sm[];
    float* xtile = sm;                  // [8][520]   (dead after feats built)
    float* h_s   = sm;                  // [64][132]  overlays xtile
    float* feats = sm + FE_OFF;         // [64][128]  feats_s[f][t]
    float* o_s   = feats;               // [128][64]  overlays feats
    float* w1t   = sm + W1_OFF;         // [64][68]   w1t[f][h] = W1[h][f]
    float* w2t   = sm + W2_OFF;         // [64][68]   w2t[h][o] = W2[o][h]
    float* b1s   = sm + B1_OFF;
    float* b2s   = sm + B2_OFF;

    const int blk = blockIdx.x;
    const int n   = blockIdx.y;
    const int tid = threadIdx.x;

    // ---- Phase 1: load x tile (coalesced) + transposed weights + biases ----
    const int xbase = PQ * blk - 6;     // x index of xtile[c][0]
    const float* xn = x + (size_t)n * CIN * LEN;
    for (int idx = tid; idx < CIN * XT_USED; idx += 256) {
        int c = idx / XT_USED, j = idx - c * XT_USED;
        int gx = xbase + j;
        float v = (gx >= 0 && gx < LEN) ? xn[c * LEN + gx] : 0.0f;
        xtile[c * XT_ROW + j] = v;
    }
    for (int idx = tid; idx < 64 * 64; idx += 256) {
        int r = idx >> 6, cc = idx & 63;      // W[r][cc]
        w1t[cc * 68 + r] = W1[idx];           // w1t[f][h]
        w2t[cc * 68 + r] = W2[idx];           // w2t[h][o]
    }
    if (tid < 64) { b1s[tid] = b1[tid]; b2s[tid] = b2[tid]; }
    __syncthreads();

    // ---- Phase 2: build feats_s[f=c*8+k][t] = xtile[c][4t+k] ----
    for (int idx = tid; idx < 64 * TPATCH; idx += 256) {
        int f = idx >> 7, t = idx & 127;
        int c = f >> 3,  k = f & 7;
        feats[f * TPATCH + t] = xtile[c * XT_ROW + 4 * t + k];
    }
    __syncthreads();

    // Thread tile: 8 patches x 4 cols
    const int tx = tid & 15, ty = tid >> 4;
    const int r0 = ty * 8;      // patch base
    const int c0 = tx * 4;      // column base

    // ---- Phase 3: GEMM1 (M=128, N=64, K=64) + bias + exact GELU -> h_s ----
    {
        float acc[8][4];
        #pragma unroll
        for (int i = 0; i < 8; i++)
            #pragma unroll
            for (int j = 0; j < 4; j++) acc[i][j] = 0.0f;

        #pragma unroll 16
        for (int fk = 0; fk < 64; fk++) {
            float4 a0 = *(const float4*)(feats + fk * TPATCH + r0);
            float4 a1 = *(const float4*)(feats + fk * TPATCH + r0 + 4);
            float4 bb = *(const float4*)(w1t + fk * 68 + c0);
            float av[8] = {a0.x, a0.y, a0.z, a0.w, a1.x, a1.y, a1.z, a1.w};
            float bv[4] = {bb.x, bb.y, bb.z, bb.w};
            #pragma unroll
            for (int i = 0; i < 8; i++)
                #pragma unroll
                for (int j = 0; j < 4; j++)
                    acc[i][j] = fmaf(av[i], bv[j], acc[i][j]);
        }
        #pragma unroll
        for (int j = 0; j < 4; j++) {
            float bias = b1s[c0 + j];
            float g[8];
            #pragma unroll
            for (int i = 0; i < 8; i++) {
                float v = acc[i][j] + bias;
                g[i] = 0.5f * v * (1.0f + erff(v * 0.70710678118654752f));
            }
            *(float4*)(h_s + (c0 + j) * HS_ROW + r0)     = make_float4(g[0], g[1], g[2], g[3]);
            *(float4*)(h_s + (c0 + j) * HS_ROW + r0 + 4) = make_float4(g[4], g[5], g[6], g[7]);
        }
    }
    __syncthreads();

    // ---- Phase 4: GEMM2 (M=128, N=64, K=64) + bias -> o_s[t][c*8+k] ----
    {
        float acc[8][4];
        #pragma unroll
        for (int i = 0; i < 8; i++)
            #pragma unroll
            for (int j = 0; j < 4; j++) acc[i][j] = 0.0f;

        #pragma unroll 16
        for (int hk = 0; hk < 64; hk++) {
            float4 a0 = *(const float4*)(h_s + hk * HS_ROW + r0);
            float4 a1 = *(const float4*)(h_s + hk * HS_ROW + r0 + 4);
            float4 bb = *(const float4*)(w2t + hk * 68 + c0);
            float av[8] = {a0.x, a0.y, a0.z, a0.w, a1.x, a1.y, a1.z, a1.w};
            float bv[4] = {bb.x, bb.y, bb.z, bb.w};
            #pragma unroll
            for (int i = 0; i < 8; i++)
                #pragma unroll
                for (int j = 0; j < 4; j++)
                    acc[i][j] = fmaf(av[i], bv[j], acc[i][j]);
        }
        #pragma unroll
        for (int i = 0; i < 8; i++) {
            float4 o;
            o.x = acc[i][0] + b2s[c0 + 0];
            o.y = acc[i][1] + b2s[c0 + 1];
            o.z = acc[i][2] + b2s[c0 + 2];
            o.w = acc[i][3] + b2s[c0 + 3];
            *(float4*)(o_s + (r0 + i) * 64 + c0) = o;
        }
    }
    __syncthreads();

    // ---- Phase 5: overlap-add + denom + crop; exclusive position range ----
    // padded position q gets: patch l1=q>>2 tap (q&3), patch l1-1 tap (q&3)+4
    const int qb    = PQ * blk;
    const int lbase = PB * blk - 1;     // l of tile patch t=0
    float* outn = out + (size_t)n * 8 * LEN;
    for (int idx = tid; idx < 8 * PQ; idx += 256) {
        int c  = idx / PQ, qq = idx - c * PQ;
        int q  = qb + qq;
        if (q < 2 || q > LEN + 1) continue;       // crop PAD=2 on each side
        int l1 = q >> 2, k1 = q & 3;
        int t1 = l1 - lbase;                       // in [1,127]
        float v = 0.0f; int cnt = 0;
        if (l1 < LOUT) { v += o_s[t1 * 64 + c * 8 + k1];           cnt++; }
        if (l1 >= 1)   { v += o_s[(t1 - 1) * 64 + c * 8 + k1 + 4]; cnt++; }
        outn[c * LEN + (q - 2)] = (cnt == 2) ? v * 0.5f : v;
    }
}

extern "C" void kernel_launch(void* const* d_in, const int* in_sizes, int n_in,
                              void* d_out, int out_size)
{
    const float* x  = (const float*)d_in[0];
    const float* W1 = (const float*)d_in[1];
    const float* b1 = (const float*)d_in[2];
    const float* W2 = (const float*)d_in[3];
    const float* b2 = (const float*)d_in[4];
    float* out = (float*)d_out;

    cudaFuncSetAttribute(fused_conv_mlp_kernel,
                         cudaFuncAttributeMaxDynamicSharedMemorySize,
                         SMEM_FLOATS * sizeof(float));
    dim3 grid(NBLK, NB);
    fused_conv_mlp_kernel<<<grid, 256, SMEM_FLOATS * sizeof(float)>>>(
        x, W1, b1, W2, b2, out);
}

// round 3
// speedup vs baseline: 1.4943x; 1.4943x over previous
#include <cuda_runtime.h>
#include <cuda_bf16.h>
#include <math.h>
#include <stdint.h>

// ---------------- problem constants ----------------
#define LEN   16384
#define LOUT  4096
#define PB    127          // primary patches per block
#define PQ    508          // exclusive padded positions per block
#define NBLK  33

// ---------------- smem layout (bytes) ----------------
// bf16 tiles use 144B row stride (72 halves): conflict-free for ldmatrix.
#define ROWB     144
#define OFF_AH   0          // A hi  [128][72] bf16  (feats, then h)
#define OFF_AL   18432      // A lo
#define OFF_W1H  36864      // W1 hi [64][72]
#define OFF_W1L  46080
#define OFF_W2H  55296
#define OFF_W2L  64512
#define OFF_B1S  73728      // float[64]
#define OFF_B2S  73984
#define OFF_XT   74240      // float[8][520]
#define SMEM_BYTES 90880
#define OFF_OS   0          // float[128][68], aliases A after GEMM2
#define OS_ROW   68
#define XT_ROW   520
#define XT_USED  516

__device__ __forceinline__ uint32_t smem_u32(const void* p) {
    uint32_t a;
    asm("{ .reg .u64 t; cvta.to.shared.u64 t, %1; cvt.u32.u64 %0, t; }"
        : "=r"(a) : "l"(p));
    return a;
}

__device__ __forceinline__ void ldsm4(uint32_t r[4], uint32_t addr) {
    asm volatile("ldmatrix.sync.aligned.m8n8.x4.shared.b16 {%0,%1,%2,%3}, [%4];"
                 : "=r"(r[0]), "=r"(r[1]), "=r"(r[2]), "=r"(r[3]) : "r"(addr));
}

__device__ __forceinline__ void mma16816(float c[4], const uint32_t a[4],
                                         const uint32_t b[2]) {
    asm volatile(
        "mma.sync.aligned.m16n8k16.row.col.f32.bf16.bf16.f32 "
        "{%0,%1,%2,%3}, {%4,%5,%6,%7}, {%8,%9}, {%0,%1,%2,%3};"
        : "+f"(c[0]), "+f"(c[1]), "+f"(c[2]), "+f"(c[3])
        : "r"(a[0]), "r"(a[1]), "r"(a[2]), "r"(a[3]), "r"(b[0]), "r"(b[1]));
}

// split two fp32 into bf16x2 hi + lo words, store at byte_off in both regions
__device__ __forceinline__ void split2_store(char* smc, float g0, float g1,
                                             int byte_off, int offHi, int offLo) {
    uint32_t ph, pl;
    asm("cvt.rn.bf16x2.f32 %0, %1, %2;" : "=r"(ph) : "f"(g1), "f"(g0));
    float h0 = __uint_as_float(ph << 16);
    float h1 = __uint_as_float(ph & 0xffff0000u);
    asm("cvt.rn.bf16x2.f32 %0, %1, %2;" : "=r"(pl) : "f"(g1 - h1), "f"(g0 - h0));
    *(uint32_t*)(smc + offHi + byte_off) = ph;
    *(uint32_t*)(smc + offLo + byte_off) = pl;
}

// 3-term split GEMM: C[8][4] += A(128x64 split) @ B(64x64 split)^T, warp tile 32x32
__device__ __forceinline__ void warp_gemm64(uint32_t sbase, int aHi, int aLo,
                                            int bHi, int bLo, int m0, int n0,
                                            int lane, float C[8][4]) {
    for (int pass = 0; pass < 3; pass++) {
        uint32_t Ab = sbase + ((pass == 2) ? aLo : aHi);
        uint32_t Bb = sbase + ((pass == 1) ? bLo : bHi);
        #pragma unroll
        for (int ks = 0; ks < 4; ks++) {
            uint32_t a[2][4], b[4][2], r[4];
            #pragma unroll
            for (int i = 0; i < 2; i++) {
                uint32_t addr = Ab + (m0 + 16 * i + (lane & 15)) * ROWB
                              + ks * 32 + (lane >> 4) * 16;
                ldsm4(a[i], addr);
            }
            #pragma unroll
            for (int jj = 0; jj < 2; jj++) {
                uint32_t addr = Bb
                    + (n0 + jj * 16 + ((lane >> 4) & 1) * 8 + (lane & 7)) * ROWB
                    + ks * 32 + ((lane >> 3) & 1) * 16;
                ldsm4(r, addr);
                b[2 * jj][0] = r[0]; b[2 * jj][1] = r[1];
                b[2 * jj + 1][0] = r[2]; b[2 * jj + 1][1] = r[3];
            }
            #pragma unroll
            for (int i = 0; i < 2; i++)
                #pragma unroll
                for (int j = 0; j < 4; j++)
                    mma16816(C[i * 4 + j], a[i], b[j]);
        }
    }
}

__global__ __launch_bounds__(256, 2)
void fused_hmma_kernel(const float* __restrict__ x,
                       const float* __restrict__ W1,
                       const float* __restrict__ b1,
                       const float* __restrict__ W2,
                       const float* __restrict__ b2,
                       float* __restrict__ out)
{
    extern __shared__ char smc[];
    const uint32_t sbase = smem_u32(smc);
    float* b1s = (float*)(smc + OFF_B1S);
    float* b2s = (float*)(smc + OFF_B2S);
    float* xt  = (float*)(smc + OFF_XT);
    float* o_s = (float*)(smc + OFF_OS);

    const int tid  = threadIdx.x;
    const int lane = tid & 31;
    const int wid  = tid >> 5;
    const int blk  = blockIdx.x;
    const int n    = blockIdx.y;
    const int wm = wid >> 1, wn = wid & 1;
    const int m0 = 32 * wm,  n0 = 32 * wn;
    const int gid = lane >> 2, tig = lane & 3;

    // ---- Phase 1: x tile (coalesced, zero-padded) + weight splits + biases ----
    const int xbase = PQ * blk - 6;
    const float* xn = x + (size_t)n * 8 * LEN;
    for (int idx = tid; idx < 8 * XT_USED; idx += 256) {
        int c = idx / XT_USED, j = idx - c * XT_USED;
        int gx = xbase + j;
        xt[c * XT_ROW + j] = (gx >= 0 && gx < LEN) ? xn[c * LEN + gx] : 0.0f;
    }
    for (int pe = tid; pe < 2048; pe += 256) {
        int nr = pe >> 5, k2 = (pe & 31) << 1;
        int bo = nr * ROWB + k2 * 2;
        split2_store(smc, W1[nr * 64 + k2], W1[nr * 64 + k2 + 1], bo, OFF_W1H, OFF_W1L);
        split2_store(smc, W2[nr * 64 + k2], W2[nr * 64 + k2 + 1], bo, OFF_W2H, OFF_W2L);
    }
    if (tid < 64) { b1s[tid] = b1[tid]; b2s[tid] = b2[tid]; }
    __syncthreads();

    // ---- Phase 2: feats[t][f] = xt[c][4t+k] split into A hi/lo ----
    for (int pe = tid; pe < 4096; pe += 256) {
        int t = pe & 127, f = (pe >> 7) << 1;
        int c = f >> 3, k = f & 7;
        float x0 = xt[c * XT_ROW + 4 * t + k];
        float x1 = xt[c * XT_ROW + 4 * t + k + 1];
        split2_store(smc, x0, x1, t * ROWB + f * 2, OFF_AH, OFF_AL);
    }
    __syncthreads();

    // ---- GEMM1: feats @ W1^T ----
    float C1[8][4];
    #pragma unroll
    for (int i = 0; i < 8; i++)
        #pragma unroll
        for (int j = 0; j < 4; j++) C1[i][j] = 0.0f;
    warp_gemm64(sbase, OFF_AH, OFF_AL, OFF_W1H, OFF_W1L, m0, n0, lane, C1);
    __syncthreads();   // all warps done reading feats before h overwrites A

    // ---- Epilogue 1: +b1, exact GELU, split -> A region ----
    #pragma unroll
    for (int i = 0; i < 2; i++) {
        #pragma unroll
        for (int j = 0; j < 4; j++) {
            float* c = C1[i * 4 + j];
            int col = n0 + 8 * j + 2 * tig;
            float bb0 = b1s[col], bb1 = b1s[col + 1];
            int row0 = m0 + 16 * i + gid;
            float v00 = c[0] + bb0, v01 = c[1] + bb1;
            float v10 = c[2] + bb0, v11 = c[3] + bb1;
            float g00 = 0.5f * v00 * (1.0f + erff(v00 * 0.70710678118654752f));
            float g01 = 0.5f * v01 * (1.0f + erff(v01 * 0.70710678118654752f));
            float g10 = 0.5f * v10 * (1.0f + erff(v10 * 0.70710678118654752f));
            float g11 = 0.5f * v11 * (1.0f + erff(v11 * 0.70710678118654752f));
            split2_store(smc, g00, g01, row0 * ROWB + col * 2, OFF_AH, OFF_AL);
            split2_store(smc, g10, g11, (row0 + 8) * ROWB + col * 2, OFF_AH, OFF_AL);
        }
    }
    __syncthreads();

    // ---- GEMM2: h @ W2^T ----
    float C2[8][4];
    #pragma unroll
    for (int i = 0; i < 8; i++)
        #pragma unroll
        for (int j = 0; j < 4; j++) C2[i][j] = 0.0f;
    warp_gemm64(sbase, OFF_AH, OFF_AL, OFF_W2H, OFF_W2L, m0, n0, lane, C2);
    __syncthreads();   // all warps done reading h before o_s (alias) overwrites

    // ---- Epilogue 2: +b2 -> o_s[t][o] fp32 ----
    #pragma unroll
    for (int i = 0; i < 2; i++) {
        #pragma unroll
        for (int j = 0; j < 4; j++) {
            float* c = C2[i * 4 + j];
            int col = n0 + 8 * j + 2 * tig;
            float bb0 = b2s[col], bb1 = b2s[col + 1];
            int row0 = m0 + 16 * i + gid;
            *(float2*)(o_s + row0 * OS_ROW + col) =
                make_float2(c[0] + bb0, c[1] + bb1);
            *(float2*)(o_s + (row0 + 8) * OS_ROW + col) =
                make_float2(c[2] + bb0, c[3] + bb1);
        }
    }
    __syncthreads();

    // ---- Phase 5: overlap-add + denom + crop (exclusive q range) ----
    const int qb = PQ * blk;
    const int lbase = PB * blk - 1;
    float* outn = out + (size_t)n * 8 * LEN;
    for (int idx = tid; idx < 8 * PQ; idx += 256) {
        int c = idx / PQ, qq = idx - c * PQ;
        int q = qb + qq;
        if (q < 2 || q > LEN + 1) continue;
        int l1 = q >> 2, k1 = q & 3;
        int t1 = l1 - lbase;
        float v = 0.0f; int cnt = 0;
        if (l1 < LOUT) { v += o_s[t1 * OS_ROW + c * 8 + k1];           cnt++; }
        if (l1 >= 1)   { v += o_s[(t1 - 1) * OS_ROW + c * 8 + k1 + 4]; cnt++; }
        outn[c * LEN + (q - 2)] = (cnt == 2) ? v * 0.5f : v;
    }
}

extern "C" void kernel_launch(void* const* d_in, const int* in_sizes, int n_in,
                              void* d_out, int out_size)
{
    const float* x  = (const float*)d_in[0];
    const float* W1 = (const float*)d_in[1];
    const float* b1 = (const float*)d_in[2];
    const float* W2 = (const float*)d_in[3];
    const float* b2 = (const float*)d_in[4];
    float* out = (float*)d_out;

    cudaFuncSetAttribute(fused_hmma_kernel,
                         cudaFuncAttributeMaxDynamicSharedMemorySize, SMEM_BYTES);
    dim3 grid(NBLK, 64);
    fused_hmma_kernel<<<grid, 256, SMEM_BYTES>>>(x, W1, b1, W2, b2, out);
}

// round 4
// speedup vs baseline: 2.2866x; 1.5303x over previous
#include <cuda_runtime.h>
#include <cuda_bf16.h>
#include <math.h>
#include <stdint.h>

// ---------------- problem constants ----------------
#define LEN   16384
#define LOUT  4096
#define PB    127          // primary patches per block
#define PQ    508          // exclusive padded positions per block
#define NBLK  33

// ---------------- smem layout (bytes) ----------------
// bf16 tiles use 144B row stride (72 halves): conflict-free for ldmatrix.
#define ROWB     144
#define OFF_AH   0          // A hi  [128][72] bf16  (feats, then h)
#define OFF_AL   18432      // A lo
#define OFF_W1H  36864      // W1 hi [64][72]
#define OFF_W1L  46080
#define OFF_W2H  55296
#define OFF_W2L  64512
#define OFF_B1S  73728      // float[64]
#define OFF_B2S  73984      // float[64]
#define SMEM_BYTES 74240
#define OFF_OS   0          // float[128][68], aliases A after GEMM2
#define OS_ROW   68

__device__ __forceinline__ uint32_t smem_u32(const void* p) {
    uint32_t a;
    asm("{ .reg .u64 t; cvta.to.shared.u64 t, %1; cvt.u32.u64 %0, t; }"
        : "=r"(a) : "l"(p));
    return a;
}

__device__ __forceinline__ void ldsm4(uint32_t r[4], uint32_t addr) {
    asm volatile("ldmatrix.sync.aligned.m8n8.x4.shared.b16 {%0,%1,%2,%3}, [%4];"
                 : "=r"(r[0]), "=r"(r[1]), "=r"(r[2]), "=r"(r[3]) : "r"(addr));
}

__device__ __forceinline__ void mma16816(float c[4], const uint32_t a[4],
                                         const uint32_t b[2]) {
    asm volatile(
        "mma.sync.aligned.m16n8k16.row.col.f32.bf16.bf16.f32 "
        "{%0,%1,%2,%3}, {%4,%5,%6,%7}, {%8,%9}, {%0,%1,%2,%3};"
        : "+f"(c[0]), "+f"(c[1]), "+f"(c[2]), "+f"(c[3])
        : "r"(a[0]), "r"(a[1]), "r"(a[2]), "r"(a[3]), "r"(b[0]), "r"(b[1]));
}

// split two fp32 into bf16x2 hi + lo words, store at byte_off in both regions
__device__ __forceinline__ void split2_store(char* smc, float g0, float g1,
                                             int byte_off, int offHi, int offLo) {
    uint32_t ph, pl;
    asm("cvt.rn.bf16x2.f32 %0, %1, %2;" : "=r"(ph) : "f"(g1), "f"(g0));
    float h0 = __uint_as_float(ph << 16);
    float h1 = __uint_as_float(ph & 0xffff0000u);
    asm("cvt.rn.bf16x2.f32 %0, %1, %2;" : "=r"(pl) : "f"(g1 - h1), "f"(g0 - h0));
    *(uint32_t*)(smc + offHi + byte_off) = ph;
    *(uint32_t*)(smc + offLo + byte_off) = pl;
}

// 3-term split GEMM with hoisted addressing. aOff/bOff are lane-resolved
// offsets within a tile; pass bases select hi/lo regions.
__device__ __forceinline__ void warp_gemm64(uint32_t sbase, int aHi, int aLo,
                                            int bHi, int bLo,
                                            uint32_t aOff, uint32_t bOff0,
                                            uint32_t bOff1, float C[8][4]) {
    #pragma unroll 1
    for (int pass = 0; pass < 3; pass++) {
        uint32_t Ab = sbase + ((pass == 2) ? aLo : aHi) + aOff;
        uint32_t Bb = sbase + ((pass == 1) ? bLo : bHi);
        uint32_t B0 = Bb + bOff0, B1 = Bb + bOff1;
        #pragma unroll
        for (int ks = 0; ks < 4; ks++) {
            uint32_t a[2][4], b[4][2], r[4];
            ldsm4(a[0], Ab + ks * 32);
            ldsm4(a[1], Ab + 16 * ROWB + ks * 32);
            ldsm4(r, B0 + ks * 32);
            b[0][0] = r[0]; b[0][1] = r[1]; b[1][0] = r[2]; b[1][1] = r[3];
            ldsm4(r, B1 + ks * 32);
            b[2][0] = r[0]; b[2][1] = r[1]; b[3][0] = r[2]; b[3][1] = r[3];
            #pragma unroll
            for (int i = 0; i < 2; i++)
                #pragma unroll
                for (int j = 0; j < 4; j++)
                    mma16816(C[i * 4 + j], a[i], b[j]);
        }
    }
}

__global__ __launch_bounds__(256, 3)
void fused_hmma_kernel(const float* __restrict__ x,
                       const float* __restrict__ W1,
                       const float* __restrict__ b1,
                       const float* __restrict__ W2,
                       const float* __restrict__ b2,
                       float* __restrict__ out)
{
    extern __shared__ char smc[];
    const uint32_t sbase = smem_u32(smc);
    float* b1s = (float*)(smc + OFF_B1S);
    float* b2s = (float*)(smc + OFF_B2S);
    float* o_s = (float*)(smc + OFF_OS);

    const int tid  = threadIdx.x;
    const int lane = tid & 31;
    const int wid  = tid >> 5;
    const int blk  = blockIdx.x;
    const int n    = blockIdx.y;
    const int wm = wid >> 1, wn = wid & 1;
    const int m0 = 32 * wm,  n0 = 32 * wn;
    const int gid = lane >> 2, tig = lane & 3;

    // lane-resolved ldmatrix offsets (hoisted out of GEMM loops)
    const uint32_t aOff  = (uint32_t)(m0 + (lane & 15)) * ROWB + (lane >> 4) * 16;
    const uint32_t bOff0 = (uint32_t)(n0 + ((lane >> 4) & 1) * 8 + (lane & 7)) * ROWB
                         + ((lane >> 3) & 1) * 16;
    const uint32_t bOff1 = bOff0 + 16 * ROWB;

    // ---- Phase 1: x -> split A directly (no staging), weights, biases ----
    {
        const float* xn = x + (size_t)n * 8 * LEN;
        const int t = tid & 127;
        const int chalf = tid >> 7;               // 0/1 -> channels 0-3 / 4-7
        const int idx0 = PQ * blk - 6 + 4 * t;    // x index of tap k=0
        const bool interior = (idx0 >= 0) && (idx0 + 7 < LEN);
        #pragma unroll
        for (int cc = 0; cc < 4; cc++) {
            int c = chalf * 4 + cc;
            const float* xp = xn + c * LEN;
            float v[8];
            if (interior) {
                #pragma unroll
                for (int jj = 0; jj < 4; jj++) {
                    float2 u = *(const float2*)(xp + idx0 + 2 * jj);
                    v[2 * jj] = u.x; v[2 * jj + 1] = u.y;
                }
            } else {
                #pragma unroll
                for (int j = 0; j < 8; j++) {
                    int ix = idx0 + j;
                    v[j] = (ix >= 0 && ix < LEN) ? xp[ix] : 0.0f;
                }
            }
            #pragma unroll
            for (int p = 0; p < 4; p++)
                split2_store(smc, v[2 * p], v[2 * p + 1],
                             t * ROWB + (c * 8 + 2 * p) * 2, OFF_AH, OFF_AL);
        }
        for (int pe = tid; pe < 2048; pe += 256) {
            int nr = pe >> 5, k2 = (pe & 31) << 1;
            int bo = nr * ROWB + k2 * 2;
            split2_store(smc, W1[nr * 64 + k2], W1[nr * 64 + k2 + 1], bo, OFF_W1H, OFF_W1L);
            split2_store(smc, W2[nr * 64 + k2], W2[nr * 64 + k2 + 1], bo, OFF_W2H, OFF_W2L);
        }
        if (tid < 64) { b1s[tid] = b1[tid]; b2s[tid] = b2[tid]; }
    }
    __syncthreads();

    // ---- GEMM1: feats @ W1^T ----
    float C1[8][4];
    #pragma unroll
    for (int i = 0; i < 8; i++)
        #pragma unroll
        for (int j = 0; j < 4; j++) C1[i][j] = 0.0f;
    warp_gemm64(sbase, OFF_AH, OFF_AL, OFF_W1H, OFF_W1L, aOff, bOff0, bOff1, C1);
    __syncthreads();   // all warps done reading feats before h overwrites A

    // ---- Epilogue 1: +b1, exact GELU, split -> A region ----
    #pragma unroll
    for (int i = 0; i < 2; i++) {
        #pragma unroll
        for (int j = 0; j < 4; j++) {
            float* c = C1[i * 4 + j];
            int col = n0 + 8 * j + 2 * tig;
            float bb0 = b1s[col], bb1 = b1s[col + 1];
            int row0 = m0 + 16 * i + gid;
            float v00 = c[0] + bb0, v01 = c[1] + bb1;
            float v10 = c[2] + bb0, v11 = c[3] + bb1;
            float g00 = 0.5f * v00 * (1.0f + erff(v00 * 0.70710678118654752f));
            float g01 = 0.5f * v01 * (1.0f + erff(v01 * 0.70710678118654752f));
            float g10 = 0.5f * v10 * (1.0f + erff(v10 * 0.70710678118654752f));
            float g11 = 0.5f * v11 * (1.0f + erff(v11 * 0.70710678118654752f));
            split2_store(smc, g00, g01, row0 * ROWB + col * 2, OFF_AH, OFF_AL);
            split2_store(smc, g10, g11, (row0 + 8) * ROWB + col * 2, OFF_AH, OFF_AL);
        }
    }
    __syncthreads();

    // ---- GEMM2: h @ W2^T ----
    float C2[8][4];
    #pragma unroll
    for (int i = 0; i < 8; i++)
        #pragma unroll
        for (int j = 0; j < 4; j++) C2[i][j] = 0.0f;
    warp_gemm64(sbase, OFF_AH, OFF_AL, OFF_W2H, OFF_W2L, aOff, bOff0, bOff1, C2);
    __syncthreads();   // all warps done reading h before o_s (alias) overwrites

    // ---- Epilogue 2: +b2 -> o_s[t][o] fp32 ----
    #pragma unroll
    for (int i = 0; i < 2; i++) {
        #pragma unroll
        for (int j = 0; j < 4; j++) {
            float* c = C2[i * 4 + j];
            int col = n0 + 8 * j + 2 * tig;
            float bb0 = b2s[col], bb1 = b2s[col + 1];
            int row0 = m0 + 16 * i + gid;
            *(float2*)(o_s + row0 * OS_ROW + col) =
                make_float2(c[0] + bb0, c[1] + bb1);
            *(float2*)(o_s + (row0 + 8) * OS_ROW + col) =
                make_float2(c[2] + bb0, c[3] + bb1);
        }
    }
    __syncthreads();

    // ---- Phase 5: overlap-add + denom + crop (exclusive q range) ----
    const int qb = PQ * blk;
    const int lbase = PB * blk - 1;
    float* outn = out + (size_t)n * 8 * LEN;
    #pragma unroll 1
    for (int c = 0; c < 8; c++) {
        for (int qq = tid; qq < PQ; qq += 256) {
            int q = qb + qq;
            if (q < 2 || q > LEN + 1) continue;
            int l1 = q >> 2, k1 = q & 3;
            int t1 = l1 - lbase;
            float v = 0.0f; int cnt = 0;
            if (l1 < LOUT) { v += o_s[t1 * OS_ROW + c * 8 + k1];           cnt++; }
            if (l1 >= 1)   { v += o_s[(t1 - 1) * OS_ROW + c * 8 + k1 + 4]; cnt++; }
            outn[c * LEN + (q - 2)] = (cnt == 2) ? v * 0.5f : v;
        }
    }
}

extern "C" void kernel_launch(void* const* d_in, const int* in_sizes, int n_in,
                              void* d_out, int out_size)
{
    const float* x  = (const float*)d_in[0];
    const float* W1 = (const float*)d_in[1];
    const float* b1 = (const float*)d_in[2];
    const float* W2 = (const float*)d_in[3];
    const float* b2 = (const float*)d_in[4];
    float* out = (float*)d_out;

    cudaFuncSetAttribute(fused_hmma_kernel,
                         cudaFuncAttributeMaxDynamicSharedMemorySize, SMEM_BYTES);
    dim3 grid(NBLK, 64);
    fused_hmma_kernel<<<grid, 256, SMEM_BYTES>>>(x, W1, b1, W2, b2, out);
}

// round 5
// speedup vs baseline: 2.5946x; 1.1347x over previous
#include <cuda_runtime.h>
#include <cuda_bf16.h>
#include <math.h>
#include <stdint.h>

// ---------------- problem constants ----------------
#define LEN   16384
#define LOUT  4096
#define PB    127          // primary patches per block
#define PQ    508          // exclusive padded positions per block
#define NBLK  33

// ---------------- smem layout (bytes) ----------------
#define ROWB     144        // bf16 row stride (72 halves): ldmatrix conflict-free
#define OFF_AH   0          // A hi  [128][72] bf16  (feats, then h)
#define OFF_AL   18432      // A lo
#define OFF_W1H  36864      // W1 hi [64][72]   (regions contiguous: W1H,W1L,W2H,W2L)
#define OFF_W1L  46080
#define OFF_W2H  55296
#define OFF_W2L  64512
#define OFF_B1S  73728      // float[64]
#define OFF_B2S  73984      // float[64]
#define SMEM_BYTES 74240
#define OFF_OS   0          // float[128][68], aliases A after GEMM2
#define OS_ROW   68

// pre-split weight image: 4 regions x 64 rows x 36 uint32 (144B rows) = 36864 B
__device__ uint4 g_wsplit4[2304];   // zero-init padding

__device__ __forceinline__ uint32_t smem_u32(const void* p) {
    uint32_t a;
    asm("{ .reg .u64 t; cvta.to.shared.u64 t, %1; cvt.u32.u64 %0, t; }"
        : "=r"(a) : "l"(p));
    return a;
}

__device__ __forceinline__ void ldsm4(uint32_t r[4], uint32_t addr) {
    asm volatile("ldmatrix.sync.aligned.m8n8.x4.shared.b16 {%0,%1,%2,%3}, [%4];"
                 : "=r"(r[0]), "=r"(r[1]), "=r"(r[2]), "=r"(r[3]) : "r"(addr));
}

__device__ __forceinline__ void mma16816(float c[4], const uint32_t a[4],
                                         const uint32_t* b) {
    asm volatile(
        "mma.sync.aligned.m16n8k16.row.col.f32.bf16.bf16.f32 "
        "{%0,%1,%2,%3}, {%4,%5,%6,%7}, {%8,%9}, {%0,%1,%2,%3};"
        : "+f"(c[0]), "+f"(c[1]), "+f"(c[2]), "+f"(c[3])
        : "r"(a[0]), "r"(a[1]), "r"(a[2]), "r"(a[3]), "r"(b[0]), "r"(b[1]));
}

__device__ __forceinline__ void split2(float g0, float g1, uint32_t& ph, uint32_t& pl) {
    asm("cvt.rn.bf16x2.f32 %0, %1, %2;" : "=r"(ph) : "f"(g1), "f"(g0));
    float h0 = __uint_as_float(ph << 16);
    float h1 = __uint_as_float(ph & 0xffff0000u);
    asm("cvt.rn.bf16x2.f32 %0, %1, %2;" : "=r"(pl) : "f"(g1 - h1), "f"(g0 - h0));
}

__device__ __forceinline__ void split2_store(char* smc, float g0, float g1,
                                             int byte_off, int offHi, int offLo) {
    uint32_t ph, pl;
    split2(g0, g1, ph, pl);
    *(uint32_t*)(smc + offHi + byte_off) = ph;
    *(uint32_t*)(smc + offLo + byte_off) = pl;
}

// ---- prep kernel: split W1/W2 fp32 -> bf16 hi/lo smem-image in global ----
__global__ void weight_split_kernel(const float* __restrict__ W1,
                                    const float* __restrict__ W2) {
    uint32_t* w = (uint32_t*)g_wsplit4;
    int i = blockIdx.x * 256 + threadIdx.x;      // 0..2047
    if (i >= 2048) return;
    int nr = i >> 5, k2 = (i & 31) << 1;
    int word = nr * 36 + (k2 >> 1);
    uint32_t h, l;
    split2(W1[nr * 64 + k2], W1[nr * 64 + k2 + 1], h, l);
    w[0 * 2304 + word] = h; w[1 * 2304 + word] = l;
    split2(W2[nr * 64 + k2], W2[nr * 64 + k2 + 1], h, l);
    w[2 * 2304 + word] = h; w[3 * 2304 + word] = l;
}

// 3-term split GEMM, fragment-reuse form: each fragment loaded once per ks.
__device__ __forceinline__ void warp_gemm64(uint32_t aH, uint32_t aL,
                                            uint32_t bH0, uint32_t bH1,
                                            uint32_t bL0, uint32_t bL1,
                                            float C[8][4]) {
    #pragma unroll
    for (int ks = 0; ks < 4; ks++) {
        uint32_t ah[2][4], al[2][4], bh[4][2], bl[4][2], r[4];
        ldsm4(ah[0], aH + ks * 32);
        ldsm4(ah[1], aH + 16 * ROWB + ks * 32);
        ldsm4(al[0], aL + ks * 32);
        ldsm4(al[1], aL + 16 * ROWB + ks * 32);
        ldsm4(r, bH0 + ks * 32);
        bh[0][0]=r[0]; bh[0][1]=r[1]; bh[1][0]=r[2]; bh[1][1]=r[3];
        ldsm4(r, bH1 + ks * 32);
        bh[2][0]=r[0]; bh[2][1]=r[1]; bh[3][0]=r[2]; bh[3][1]=r[3];
        ldsm4(r, bL0 + ks * 32);
        bl[0][0]=r[0]; bl[0][1]=r[1]; bl[1][0]=r[2]; bl[1][1]=r[3];
        ldsm4(r, bL1 + ks * 32);
        bl[2][0]=r[0]; bl[2][1]=r[1]; bl[3][0]=r[2]; bl[3][1]=r[3];
        #pragma unroll
        for (int i = 0; i < 2; i++)
            #pragma unroll
            for (int j = 0; j < 4; j++) {
                mma16816(C[i * 4 + j], ah[i], bh[j]);
                mma16816(C[i * 4 + j], ah[i], bl[j]);
                mma16816(C[i * 4 + j], al[i], bh[j]);
            }
    }
}

__global__ __launch_bounds__(256, 3)
void fused_hmma_kernel(const float* __restrict__ x,
                       const float* __restrict__ b1,
                       const float* __restrict__ b2,
                       float* __restrict__ out)
{
    extern __shared__ char smc[];
    const uint32_t sbase = smem_u32(smc);
    float* b1s = (float*)(smc + OFF_B1S);
    float* b2s = (float*)(smc + OFF_B2S);
    float* o_s = (float*)(smc + OFF_OS);

    const int tid  = threadIdx.x;
    const int lane = tid & 31;
    const int wid  = tid >> 5;
    const int blk  = blockIdx.x;
    const int n    = blockIdx.y;
    const int wm = wid >> 1, wn = wid & 1;
    const int m0 = 32 * wm,  n0 = 32 * wn;
    const int gid = lane >> 2, tig = lane & 3;

    // lane-resolved ldmatrix offsets
    const uint32_t aOff  = (uint32_t)(m0 + (lane & 15)) * ROWB + (lane >> 4) * 16;
    const uint32_t bOff0 = (uint32_t)(n0 + ((lane >> 4) & 1) * 8 + (lane & 7)) * ROWB
                         + ((lane >> 3) & 1) * 16;
    const uint32_t bOff1 = bOff0 + 16 * ROWB;

    // ---- Phase 1: x -> split A directly; weights via pre-split copy ----
    {
        const float* xn = x + (size_t)n * 8 * LEN;
        const int t = tid & 127;
        const int chalf = tid >> 7;               // 0/1 -> channels 0-3 / 4-7
        const int idx0 = PQ * blk - 6 + 4 * t;    // x index of tap k=0
        const bool interior = (idx0 >= 0) && (idx0 + 7 < LEN);
        #pragma unroll
        for (int cc = 0; cc < 4; cc++) {
            int c = chalf * 4 + cc;
            const float* xp = xn + c * LEN;
            float v[8];
            if (interior) {
                #pragma unroll
                for (int jj = 0; jj < 4; jj++) {
                    float2 u = *(const float2*)(xp + idx0 + 2 * jj);
                    v[2 * jj] = u.x; v[2 * jj + 1] = u.y;
                }
            } else {
                #pragma unroll
                for (int j = 0; j < 8; j++) {
                    int ix = idx0 + j;
                    v[j] = (ix >= 0 && ix < LEN) ? xp[ix] : 0.0f;
                }
            }
            #pragma unroll
            for (int p = 0; p < 4; p++)
                split2_store(smc, v[2 * p], v[2 * p + 1],
                             t * ROWB + (c * 8 + 2 * p) * 2, OFF_AH, OFF_AL);
        }
        uint4* wdst = (uint4*)(smc + OFF_W1H);
        #pragma unroll
        for (int i = 0; i < 9; i++)
            wdst[tid + 256 * i] = g_wsplit4[tid + 256 * i];
        if (tid < 64) { b1s[tid] = b1[tid]; b2s[tid] = b2[tid]; }
    }
    __syncthreads();

    // ---- GEMM1: feats @ W1^T ----
    float C1[8][4];
    #pragma unroll
    for (int i = 0; i < 8; i++)
        #pragma unroll
        for (int j = 0; j < 4; j++) C1[i][j] = 0.0f;
    warp_gemm64(sbase + OFF_AH + aOff, sbase + OFF_AL + aOff,
                sbase + OFF_W1H + bOff0, sbase + OFF_W1H + bOff1,
                sbase + OFF_W1L + bOff0, sbase + OFF_W1L + bOff1, C1);
    // pair barrier: only the 2 warps sharing this M-band touch these rows
    asm volatile("bar.sync %0, 64;" :: "r"(wm + 1) : "memory");

    // ---- Epilogue 1: +b1, exact GELU, split -> A region (own band) ----
    #pragma unroll
    for (int i = 0; i < 2; i++) {
        #pragma unroll
        for (int j = 0; j < 4; j++) {
            float* c = C1[i * 4 + j];
            int col = n0 + 8 * j + 2 * tig;
            float bb0 = b1s[col], bb1 = b1s[col + 1];
            int row0 = m0 + 16 * i + gid;
            float v00 = c[0] + bb0, v01 = c[1] + bb1;
            float v10 = c[2] + bb0, v11 = c[3] + bb1;
            float g00 = 0.5f * v00 * (1.0f + erff(v00 * 0.70710678118654752f));
            float g01 = 0.5f * v01 * (1.0f + erff(v01 * 0.70710678118654752f));
            float g10 = 0.5f * v10 * (1.0f + erff(v10 * 0.70710678118654752f));
            float g11 = 0.5f * v11 * (1.0f + erff(v11 * 0.70710678118654752f));
            split2_store(smc, g00, g01, row0 * ROWB + col * 2, OFF_AH, OFF_AL);
            split2_store(smc, g10, g11, (row0 + 8) * ROWB + col * 2, OFF_AH, OFF_AL);
        }
    }
    asm volatile("bar.sync %0, 64;" :: "r"(wm + 1) : "memory");

    // ---- GEMM2: h @ W2^T ----
    float C2[8][4];
    #pragma unroll
    for (int i = 0; i < 8; i++)
        #pragma unroll
        for (int j = 0; j < 4; j++) C2[i][j] = 0.0f;
    warp_gemm64(sbase + OFF_AH + aOff, sbase + OFF_AL + aOff,
                sbase + OFF_W2H + bOff0, sbase + OFF_W2H + bOff1,
                sbase + OFF_W2L + bOff0, sbase + OFF_W2L + bOff1, C2);
    __syncthreads();   // o_s (alias) spans other bands' h rows

    // ---- Epilogue 2: +b2 -> o_s[t][o] fp32 ----
    #pragma unroll
    for (int i = 0; i < 2; i++) {
        #pragma unroll
        for (int j = 0; j < 4; j++) {
            float* c = C2[i * 4 + j];
            int col = n0 + 8 * j + 2 * tig;
            float bb0 = b2s[col], bb1 = b2s[col + 1];
            int row0 = m0 + 16 * i + gid;
            *(float2*)(o_s + row0 * OS_ROW + col) =
                make_float2(c[0] + bb0, c[1] + bb1);
            *(float2*)(o_s + (row0 + 8) * OS_ROW + col) =
                make_float2(c[2] + bb0, c[3] + bb1);
        }
    }
    __syncthreads();

    // ---- Phase 5: overlap-add + denom + crop (exclusive q range) ----
    const int qb = PQ * blk;
    const int lbase = PB * blk - 1;
    float* outn = out + (size_t)n * 8 * LEN;
    #pragma unroll 1
    for (int c = 0; c < 8; c++) {
        for (int qq = tid; qq < PQ; qq += 256) {
            int q = qb + qq;
            if (q < 2 || q > LEN + 1) continue;
            int l1 = q >> 2, k1 = q & 3;
            int t1 = l1 - lbase;
            float v = 0.0f; int cnt = 0;
            if (l1 < LOUT) { v += o_s[t1 * OS_ROW + c * 8 + k1];           cnt++; }
            if (l1 >= 1)   { v += o_s[(t1 - 1) * OS_ROW + c * 8 + k1 + 4]; cnt++; }
            outn[c * LEN + (q - 2)] = (cnt == 2) ? v * 0.5f : v;
        }
    }
}

extern "C" void kernel_launch(void* const* d_in, const int* in_sizes, int n_in,
                              void* d_out, int out_size)
{
    const float* x  = (const float*)d_in[0];
    const float* W1 = (const float*)d_in[1];
    const float* b1 = (const float*)d_in[2];
    const float* W2 = (const float*)d_in[3];
    const float* b2 = (const float*)d_in[4];
    float* out = (float*)d_out;

    weight_split_kernel<<<8, 256>>>(W1, W2);

    cudaFuncSetAttribute(fused_hmma_kernel,
                         cudaFuncAttributeMaxDynamicSharedMemorySize, SMEM_BYTES);
    dim3 grid(NBLK, 64);
    fused_hmma_kernel<<<grid, 256, SMEM_BYTES>>>(x, b1, b2, out);
}

// round 6
// speedup vs baseline: 3.0500x; 1.1755x over previous
#include <cuda_runtime.h>
#include <cuda_fp16.h>
#include <math.h>
#include <stdint.h>

// ---------------- problem constants ----------------
#define LEN   16384
#define LOUT  4096
#define PB    127          // primary patches per block
#define PQ    508          // exclusive padded positions per block
#define NBLK  33

// ---------------- smem layout (bytes) ----------------
#define ROWB     144        // fp16 row stride (72 halves): ldmatrix conflict-free
#define OFF_A    0          // A fp16 [128][72]  (feats, then h)
#define OFF_W1H  18432      // W hi/lo regions contiguous, each 64x72 fp16 = 9216B
#define OFF_W1L  27648
#define OFF_W2H  36864
#define OFF_W2L  46080
#define OFF_B1S  55296      // float[64]
#define OFF_B2S  55552      // float[64]
#define SMEM_BYTES 55808
#define OFF_OS   0          // float[128][68] = 34816B, aliases A+W1h+W1l (dead then)
#define OS_ROW   68

// pre-split weight image: 4 regions x 64 rows x 36 words = 2304 uint4
__device__ uint4 g_wsplit4[2304];

__device__ __forceinline__ uint32_t smem_u32(const void* p) {
    uint32_t a;
    asm("{ .reg .u64 t; cvta.to.shared.u64 t, %1; cvt.u32.u64 %0, t; }"
        : "=r"(a) : "l"(p));
    return a;
}

__device__ __forceinline__ void ldsm4(uint32_t r[4], uint32_t addr) {
    asm volatile("ldmatrix.sync.aligned.m8n8.x4.shared.b16 {%0,%1,%2,%3}, [%4];"
                 : "=r"(r[0]), "=r"(r[1]), "=r"(r[2]), "=r"(r[3]) : "r"(addr));
}

__device__ __forceinline__ void mma16816(float c[4], const uint32_t a[4],
                                         const uint32_t* b) {
    asm volatile(
        "mma.sync.aligned.m16n8k16.row.col.f32.f16.f16.f32 "
        "{%0,%1,%2,%3}, {%4,%5,%6,%7}, {%8,%9}, {%0,%1,%2,%3};"
        : "+f"(c[0]), "+f"(c[1]), "+f"(c[2]), "+f"(c[3])
        : "r"(a[0]), "r"(a[1]), "r"(a[2]), "r"(a[3]), "r"(b[0]), "r"(b[1]));
}

__device__ __forceinline__ uint32_t pack_h2(float g0, float g1) {
    uint32_t p;
    asm("cvt.rn.f16x2.f32 %0, %1, %2;" : "=r"(p) : "f"(g1), "f"(g0));
    return p;
}

// fp32 pair -> fp16 hi word + fp16 lo (residual) word
__device__ __forceinline__ void split2h(float g0, float g1,
                                        uint32_t& ph, uint32_t& pl) {
    ph = pack_h2(g0, g1);
    float h0, h1;
    asm("{ .reg .f16 a, b; mov.b32 {a, b}, %2; cvt.f32.f16 %0, a; cvt.f32.f16 %1, b; }"
        : "=f"(h0), "=f"(h1) : "r"(ph));
    pl = pack_h2(g0 - h0, g1 - h1);
}

// ---- prep kernel: split W1/W2 fp32 -> fp16 hi/lo smem-image in global ----
__global__ void weight_split_kernel(const float* __restrict__ W1,
                                    const float* __restrict__ W2) {
    uint32_t* w = (uint32_t*)g_wsplit4;
    int i = blockIdx.x * 256 + threadIdx.x;      // 0..2047
    if (i >= 2048) return;
    int nr = i >> 5, k2 = (i & 31) << 1;
    int word = nr * 36 + (k2 >> 1);
    uint32_t h, l;
    split2h(W1[nr * 64 + k2], W1[nr * 64 + k2 + 1], h, l);
    w[0 * 2304 + word] = h; w[1 * 2304 + word] = l;
    split2h(W2[nr * 64 + k2], W2[nr * 64 + k2 + 1], h, l);
    w[2 * 2304 + word] = h; w[3 * 2304 + word] = l;
}

// 2-term GEMM: C += A (fp16) @ (Wh + Wl)^T.  bh-then-bl keeps regs low.
__device__ __forceinline__ void warp_gemm64(uint32_t aB, uint32_t bH0, uint32_t bH1,
                                            uint32_t bL0, uint32_t bL1,
                                            float C[8][4]) {
    #pragma unroll
    for (int ks = 0; ks < 4; ks++) {
        uint32_t a[2][4], b[4][2], r[4];
        ldsm4(a[0], aB + ks * 32);
        ldsm4(a[1], aB + 16 * ROWB + ks * 32);
        ldsm4(r, bH0 + ks * 32);
        b[0][0]=r[0]; b[0][1]=r[1]; b[1][0]=r[2]; b[1][1]=r[3];
        ldsm4(r, bH1 + ks * 32);
        b[2][0]=r[0]; b[2][1]=r[1]; b[3][0]=r[2]; b[3][1]=r[3];
        #pragma unroll
        for (int i = 0; i < 2; i++)
            #pragma unroll
            for (int j = 0; j < 4; j++)
                mma16816(C[i * 4 + j], a[i], b[j]);
        ldsm4(r, bL0 + ks * 32);
        b[0][0]=r[0]; b[0][1]=r[1]; b[1][0]=r[2]; b[1][1]=r[3];
        ldsm4(r, bL1 + ks * 32);
        b[2][0]=r[0]; b[2][1]=r[1]; b[3][0]=r[2]; b[3][1]=r[3];
        #pragma unroll
        for (int i = 0; i < 2; i++)
            #pragma unroll
            for (int j = 0; j < 4; j++)
                mma16816(C[i * 4 + j], a[i], b[j]);
    }
}

__global__ __launch_bounds__(256, 4)
void fused_hmma_kernel(const float* __restrict__ x,
                       const float* __restrict__ b1,
                       const float* __restrict__ b2,
                       float* __restrict__ out)
{
    extern __shared__ char smc[];
    const uint32_t sbase = smem_u32(smc);
    float* b1s = (float*)(smc + OFF_B1S);
    float* b2s = (float*)(smc + OFF_B2S);
    float* o_s = (float*)(smc + OFF_OS);

    const int tid  = threadIdx.x;
    const int lane = tid & 31;
    const int wid  = tid >> 5;
    const int blk  = blockIdx.x;
    const int n    = blockIdx.y;
    const int wm = wid >> 1, wn = wid & 1;
    const int m0 = 32 * wm,  n0 = 32 * wn;
    const int gid = lane >> 2, tig = lane & 3;

    // lane-resolved ldmatrix offsets
    const uint32_t aOff  = (uint32_t)(m0 + (lane & 15)) * ROWB + (lane >> 4) * 16;
    const uint32_t bOff0 = (uint32_t)(n0 + ((lane >> 4) & 1) * 8 + (lane & 7)) * ROWB
                         + ((lane >> 3) & 1) * 16;
    const uint32_t bOff1 = bOff0 + 16 * ROWB;

    // ---- Phase 1: x -> fp16 A tile (1 STS.128 per c); weights via copy ----
    {
        const float* xn = x + (size_t)n * 8 * LEN;
        const int t = tid & 127;
        const int chalf = tid >> 7;               // 0/1 -> channels 0-3 / 4-7
        const int idx0 = PQ * blk - 6 + 4 * t;    // x index of tap k=0
        const bool interior = (idx0 >= 0) && (idx0 + 7 < LEN);
        #pragma unroll
        for (int cc = 0; cc < 4; cc++) {
            int c = chalf * 4 + cc;
            const float* xp = xn + c * LEN;
            float v[8];
            if (interior) {
                #pragma unroll
                for (int jj = 0; jj < 4; jj++) {
                    float2 u = *(const float2*)(xp + idx0 + 2 * jj);
                    v[2 * jj] = u.x; v[2 * jj + 1] = u.y;
                }
            } else {
                #pragma unroll
                for (int j = 0; j < 8; j++) {
                    int ix = idx0 + j;
                    v[j] = (ix >= 0 && ix < LEN) ? xp[ix] : 0.0f;
                }
            }
            uint4 w;
            w.x = pack_h2(v[0], v[1]); w.y = pack_h2(v[2], v[3]);
            w.z = pack_h2(v[4], v[5]); w.w = pack_h2(v[6], v[7]);
            *(uint4*)(smc + OFF_A + t * ROWB + c * 16) = w;
        }
        uint4* wdst = (uint4*)(smc + OFF_W1H);
        #pragma unroll
        for (int i = 0; i < 9; i++)
            wdst[tid + 256 * i] = g_wsplit4[tid + 256 * i];
        if (tid < 64) { b1s[tid] = b1[tid]; b2s[tid] = b2[tid]; }
    }
    __syncthreads();

    // ---- GEMM1: feats @ W1^T ----
    float C1[8][4];
    #pragma unroll
    for (int i = 0; i < 8; i++)
        #pragma unroll
        for (int j = 0; j < 4; j++) C1[i][j] = 0.0f;
    warp_gemm64(sbase + OFF_A + aOff,
                sbase + OFF_W1H + bOff0, sbase + OFF_W1H + bOff1,
                sbase + OFF_W1L + bOff0, sbase + OFF_W1L + bOff1, C1);
    // pair barrier: only the 2 warps of this M-band read/write these A rows
    asm volatile("bar.sync %0, 64;" :: "r"(wm + 1) : "memory");

    // ---- Epilogue 1: +b1, exact GELU -> fp16 A region (own band) ----
    #pragma unroll
    for (int i = 0; i < 2; i++) {
        #pragma unroll
        for (int j = 0; j < 4; j++) {
            float* c = C1[i * 4 + j];
            int col = n0 + 8 * j + 2 * tig;
            float bb0 = b1s[col], bb1 = b1s[col + 1];
            int row0 = m0 + 16 * i + gid;
            float v00 = c[0] + bb0, v01 = c[1] + bb1;
            float v10 = c[2] + bb0, v11 = c[3] + bb1;
            float g00 = 0.5f * v00 * (1.0f + erff(v00 * 0.70710678118654752f));
            float g01 = 0.5f * v01 * (1.0f + erff(v01 * 0.70710678118654752f));
            float g10 = 0.5f * v10 * (1.0f + erff(v10 * 0.70710678118654752f));
            float g11 = 0.5f * v11 * (1.0f + erff(v11 * 0.70710678118654752f));
            *(uint32_t*)(smc + OFF_A + row0 * ROWB + col * 2) = pack_h2(g00, g01);
            *(uint32_t*)(smc + OFF_A + (row0 + 8) * ROWB + col * 2) = pack_h2(g10, g11);
        }
    }
    asm volatile("bar.sync %0, 64;" :: "r"(wm + 1) : "memory");

    // ---- GEMM2: h @ W2^T ----
    float C2[8][4];
    #pragma unroll
    for (int i = 0; i < 8; i++)
        #pragma unroll
        for (int j = 0; j < 4; j++) C2[i][j] = 0.0f;
    warp_gemm64(sbase + OFF_A + aOff,
                sbase + OFF_W2H + bOff0, sbase + OFF_W2H + bOff1,
                sbase + OFF_W2L + bOff0, sbase + OFF_W2L + bOff1, C2);
    __syncthreads();   // o_s aliases A+W1 regions across all bands

    // ---- Epilogue 2: +b2 -> o_s[t][o] fp32 ----
    #pragma unroll
    for (int i = 0; i < 2; i++) {
        #pragma unroll
        for (int j = 0; j < 4; j++) {
            float* c = C2[i * 4 + j];
            int col = n0 + 8 * j + 2 * tig;
            float bb0 = b2s[col], bb1 = b2s[col + 1];
            int row0 = m0 + 16 * i + gid;
            *(float2*)(o_s + row0 * OS_ROW + col) =
                make_float2(c[0] + bb0, c[1] + bb1);
            *(float2*)(o_s + (row0 + 8) * OS_ROW + col) =
                make_float2(c[2] + bb0, c[3] + bb1);
        }
    }
    __syncthreads();

    // ---- Phase 5: overlap-add + denom + crop (exclusive q range) ----
    const int qb = PQ * blk;
    const int lbase = PB * blk - 1;
    float* outn = out + (size_t)n * 8 * LEN;
    #pragma unroll 1
    for (int c = 0; c < 8; c++) {
        for (int qq = tid; qq < PQ; qq += 256) {
            int q = qb + qq;
            if (q < 2 || q > LEN + 1) continue;
            int l1 = q >> 2, k1 = q & 3;
            int t1 = l1 - lbase;
            float v = 0.0f; int cnt = 0;
            if (l1 < LOUT) { v += o_s[t1 * OS_ROW + c * 8 + k1];           cnt++; }
            if (l1 >= 1)   { v += o_s[(t1 - 1) * OS_ROW + c * 8 + k1 + 4]; cnt++; }
            outn[c * LEN + (q - 2)] = (cnt == 2) ? v * 0.5f : v;
        }
    }
}

extern "C" void kernel_launch(void* const* d_in, const int* in_sizes, int n_in,
                              void* d_out, int out_size)
{
    const float* x  = (const float*)d_in[0];
    const float* W1 = (const float*)d_in[1];
    const float* b1 = (const float*)d_in[2];
    const float* W2 = (const float*)d_in[3];
    const float* b2 = (const float*)d_in[4];
    float* out = (float*)d_out;

    weight_split_kernel<<<8, 256>>>(W1, W2);

    cudaFuncSetAttribute(fused_hmma_kernel,
                         cudaFuncAttributeMaxDynamicSharedMemorySize, SMEM_BYTES);
    dim3 grid(NBLK, 64);
    fused_hmma_kernel<<<grid, 256, SMEM_BYTES>>>(x, b1, b2, out);
}

// round 7
// speedup vs baseline: 3.6441x; 1.1948x over previous
#include <cuda_runtime.h>
#include <cuda_fp16.h>
#include <math.h>
#include <stdint.h>

// ---------------- problem constants ----------------
#define LEN   16384
#define LOUT  4096
#define PB    127          // primary patches per block
#define PQ    508          // exclusive padded positions per block
#define NBLK  33

// ---------------- smem layout (bytes) ----------------
#define ROWB     144        // fp16 row stride (72 halves): ldmatrix conflict-free
#define OFF_A    0          // A fp16 [128][72]  (feats, then h)
#define OFF_W1H  18432      // W hi/lo regions contiguous, each 64x72 fp16 = 9216B
#define OFF_W1L  27648
#define OFF_W2H  36864
#define OFF_W2L  46080
#define OFF_B1S  55296      // float[64]
#define OFF_B2S  55552      // float[64]
#define SMEM_BYTES 55808
#define OFF_OS   0          // float[128][68] = 34816B, aliases A+W1h+W1l (dead then)
#define OS_ROW   68

// pre-split weight image: 4 regions x 64 rows x 36 words = 2304 uint4
__device__ uint4 g_wsplit4[2304];

__device__ __forceinline__ uint32_t smem_u32(const void* p) {
    uint32_t a;
    asm("{ .reg .u64 t; cvta.to.shared.u64 t, %1; cvt.u32.u64 %0, t; }"
        : "=r"(a) : "l"(p));
    return a;
}

__device__ __forceinline__ void ldsm4(uint32_t r[4], uint32_t addr) {
    asm volatile("ldmatrix.sync.aligned.m8n8.x4.shared.b16 {%0,%1,%2,%3}, [%4];"
                 : "=r"(r[0]), "=r"(r[1]), "=r"(r[2]), "=r"(r[3]) : "r"(addr));
}

__device__ __forceinline__ void mma16816(float c[4], const uint32_t a[4],
                                         const uint32_t* b) {
    asm volatile(
        "mma.sync.aligned.m16n8k16.row.col.f32.f16.f16.f32 "
        "{%0,%1,%2,%3}, {%4,%5,%6,%7}, {%8,%9}, {%0,%1,%2,%3};"
        : "+f"(c[0]), "+f"(c[1]), "+f"(c[2]), "+f"(c[3])
        : "r"(a[0]), "r"(a[1]), "r"(a[2]), "r"(a[3]), "r"(b[0]), "r"(b[1]));
}

__device__ __forceinline__ uint32_t pack_h2(float g0, float g1) {
    uint32_t p;
    asm("cvt.rn.f16x2.f32 %0, %1, %2;" : "=r"(p) : "f"(g1), "f"(g0));
    return p;
}

// fp32 pair -> fp16 hi word + fp16 lo (residual) word
__device__ __forceinline__ void split2h(float g0, float g1,
                                        uint32_t& ph, uint32_t& pl) {
    ph = pack_h2(g0, g1);
    float h0, h1;
    asm("{ .reg .f16 a, b; mov.b32 {a, b}, %2; cvt.f32.f16 %0, a; cvt.f32.f16 %1, b; }"
        : "=f"(h0), "=f"(h1) : "r"(ph));
    pl = pack_h2(g0 - h0, g1 - h1);
}

// ---- prep kernel: split W1/W2 fp32 -> fp16 hi/lo smem-image in global ----
__global__ void weight_split_kernel(const float* __restrict__ W1,
                                    const float* __restrict__ W2) {
    uint32_t* w = (uint32_t*)g_wsplit4;
    int i = blockIdx.x * 256 + threadIdx.x;      // 0..2047
    if (i >= 2048) return;
    int nr = i >> 5, k2 = (i & 31) << 1;
    int word = nr * 36 + (k2 >> 1);
    uint32_t h, l;
    split2h(W1[nr * 64 + k2], W1[nr * 64 + k2 + 1], h, l);
    w[0 * 2304 + word] = h; w[1 * 2304 + word] = l;
    split2h(W2[nr * 64 + k2], W2[nr * 64 + k2 + 1], h, l);
    w[2 * 2304 + word] = h; w[3 * 2304 + word] = l;
}

// 2-term GEMM: C += A (fp16) @ (Wh + Wl)^T.  bh-then-bl keeps regs low.
__device__ __forceinline__ void warp_gemm64(uint32_t aB, uint32_t bH0, uint32_t bH1,
                                            uint32_t bL0, uint32_t bL1,
                                            float C[8][4]) {
    #pragma unroll
    for (int ks = 0; ks < 4; ks++) {
        uint32_t a[2][4], b[4][2], r[4];
        ldsm4(a[0], aB + ks * 32);
        ldsm4(a[1], aB + 16 * ROWB + ks * 32);
        ldsm4(r, bH0 + ks * 32);
        b[0][0]=r[0]; b[0][1]=r[1]; b[1][0]=r[2]; b[1][1]=r[3];
        ldsm4(r, bH1 + ks * 32);
        b[2][0]=r[0]; b[2][1]=r[1]; b[3][0]=r[2]; b[3][1]=r[3];
        #pragma unroll
        for (int i = 0; i < 2; i++)
            #pragma unroll
            for (int j = 0; j < 4; j++)
                mma16816(C[i * 4 + j], a[i], b[j]);
        ldsm4(r, bL0 + ks * 32);
        b[0][0]=r[0]; b[0][1]=r[1]; b[1][0]=r[2]; b[1][1]=r[3];
        ldsm4(r, bL1 + ks * 32);
        b[2][0]=r[0]; b[2][1]=r[1]; b[3][0]=r[2]; b[3][1]=r[3];
        #pragma unroll
        for (int i = 0; i < 2; i++)
            #pragma unroll
            for (int j = 0; j < 4; j++)
                mma16816(C[i * 4 + j], a[i], b[j]);
    }
}

__global__ __launch_bounds__(256, 4)
void fused_hmma_kernel(const float* __restrict__ x,
                       const float* __restrict__ b1,
                       const float* __restrict__ b2,
                       float* __restrict__ out)
{
    extern __shared__ char smc[];
    const uint32_t sbase = smem_u32(smc);
    float* b1s = (float*)(smc + OFF_B1S);
    float* b2s = (float*)(smc + OFF_B2S);
    float* o_s = (float*)(smc + OFF_OS);

    const int tid  = threadIdx.x;
    const int lane = tid & 31;
    const int wid  = tid >> 5;
    const int blk  = blockIdx.x;
    const int n    = blockIdx.y;
    const int wm = wid >> 1, wn = wid & 1;
    const int m0 = 32 * wm,  n0 = 32 * wn;
    const int gid = lane >> 2, tig = lane & 3;

    // lane-resolved ldmatrix offsets
    const uint32_t aOff  = (uint32_t)(m0 + (lane & 15)) * ROWB + (lane >> 4) * 16;
    const uint32_t bOff0 = (uint32_t)(n0 + ((lane >> 4) & 1) * 8 + (lane & 7)) * ROWB
                         + ((lane >> 3) & 1) * 16;
    const uint32_t bOff1 = bOff0 + 16 * ROWB;

    // ---- Phase 1: x -> fp16 A tile (1 STS.128 per c); weights via copy ----
    {
        const float* xn = x + (size_t)n * 8 * LEN;
        const int t = tid & 127;
        const int chalf = tid >> 7;               // 0/1 -> channels 0-3 / 4-7
        const int idx0 = PQ * blk - 6 + 4 * t;    // x index of tap k=0
        const bool interior = (idx0 >= 0) && (idx0 + 7 < LEN);
        #pragma unroll
        for (int cc = 0; cc < 4; cc++) {
            int c = chalf * 4 + cc;
            const float* xp = xn + c * LEN;
            float v[8];
            if (interior) {
                #pragma unroll
                for (int jj = 0; jj < 4; jj++) {
                    float2 u = *(const float2*)(xp + idx0 + 2 * jj);
                    v[2 * jj] = u.x; v[2 * jj + 1] = u.y;
                }
            } else {
                #pragma unroll
                for (int j = 0; j < 8; j++) {
                    int ix = idx0 + j;
                    v[j] = (ix >= 0 && ix < LEN) ? xp[ix] : 0.0f;
                }
            }
            uint4 w;
            w.x = pack_h2(v[0], v[1]); w.y = pack_h2(v[2], v[3]);
            w.z = pack_h2(v[4], v[5]); w.w = pack_h2(v[6], v[7]);
            *(uint4*)(smc + OFF_A + t * ROWB + c * 16) = w;
        }
        uint4* wdst = (uint4*)(smc + OFF_W1H);
        #pragma unroll
        for (int i = 0; i < 9; i++)
            wdst[tid + 256 * i] = g_wsplit4[tid + 256 * i];
        if (tid < 64) { b1s[tid] = b1[tid]; b2s[tid] = b2[tid]; }
    }
    __syncthreads();

    // ---- GEMM1: feats @ W1^T ----
    float C1[8][4];
    #pragma unroll
    for (int i = 0; i < 8; i++)
        #pragma unroll
        for (int j = 0; j < 4; j++) C1[i][j] = 0.0f;
    warp_gemm64(sbase + OFF_A + aOff,
                sbase + OFF_W1H + bOff0, sbase + OFF_W1H + bOff1,
                sbase + OFF_W1L + bOff0, sbase + OFF_W1L + bOff1, C1);
    // pair barrier: only the 2 warps of this M-band read/write these A rows
    asm volatile("bar.sync %0, 64;" :: "r"(wm + 1) : "memory");

    // ---- Epilogue 1: +b1, exact GELU -> fp16 A region (own band) ----
    #pragma unroll
    for (int i = 0; i < 2; i++) {
        #pragma unroll
        for (int j = 0; j < 4; j++) {
            float* c = C1[i * 4 + j];
            int col = n0 + 8 * j + 2 * tig;
            float bb0 = b1s[col], bb1 = b1s[col + 1];
            int row0 = m0 + 16 * i + gid;
            float v00 = c[0] + bb0, v01 = c[1] + bb1;
            float v10 = c[2] + bb0, v11 = c[3] + bb1;
            float g00 = 0.5f * v00 * (1.0f + erff(v00 * 0.70710678118654752f));
            float g01 = 0.5f * v01 * (1.0f + erff(v01 * 0.70710678118654752f));
            float g10 = 0.5f * v10 * (1.0f + erff(v10 * 0.70710678118654752f));
            float g11 = 0.5f * v11 * (1.0f + erff(v11 * 0.70710678118654752f));
            *(uint32_t*)(smc + OFF_A + row0 * ROWB + col * 2) = pack_h2(g00, g01);
            *(uint32_t*)(smc + OFF_A + (row0 + 8) * ROWB + col * 2) = pack_h2(g10, g11);
        }
    }
    asm volatile("bar.sync %0, 64;" :: "r"(wm + 1) : "memory");

    // ---- GEMM2: h @ W2^T ----
    float C2[8][4];
    #pragma unroll
    for (int i = 0; i < 8; i++)
        #pragma unroll
        for (int j = 0; j < 4; j++) C2[i][j] = 0.0f;
    warp_gemm64(sbase + OFF_A + aOff,
                sbase + OFF_W2H + bOff0, sbase + OFF_W2H + bOff1,
                sbase + OFF_W2L + bOff0, sbase + OFF_W2L + bOff1, C2);
    __syncthreads();   // o_s aliases A+W1 regions across all bands

    // ---- Epilogue 2: +b2 -> o_s[t][o] fp32 ----
    #pragma unroll
    for (int i = 0; i < 2; i++) {
        #pragma unroll
        for (int j = 0; j < 4; j++) {
            float* c = C2[i * 4 + j];
            int col = n0 + 8 * j + 2 * tig;
            float bb0 = b2s[col], bb1 = b2s[col + 1];
            int row0 = m0 + 16 * i + gid;
            *(float2*)(o_s + row0 * OS_ROW + col) =
                make_float2(c[0] + bb0, c[1] + bb1);
            *(float2*)(o_s + (row0 + 8) * OS_ROW + col) =
                make_float2(c[2] + bb0, c[3] + bb1);
        }
    }
    __syncthreads();

    // ---- Phase 5: vectorized overlap-add. Group = 4 outputs of one l1 ----
    // out[4*l1-2 .. 4*l1+1] <- 0.5*(o_s[t1][c8+k] + o_s[t1-1][c8+k+4]), k=0..3
    // Interior groups (1 <= l1 <= 4095): both patches valid, denom = 2.
    const int lbase = PB * blk - 1;
    float* outn = out + (size_t)n * 8 * LEN;
    #pragma unroll
    for (int it = 0; it < 4; it++) {
        int g = tid + it * 256;          // 0..1023: c = g>>7, gi = g&127
        int gi = g & 127;                // t1
        if (gi == 0) continue;
        int c = g >> 7;
        int l1 = lbase + gi;
        float* orow = outn + c * LEN;
        if (l1 >= 1 && l1 <= LOUT - 1) {
            float4 a1 = *(float4*)(o_s + gi * OS_ROW + c * 8);
            float4 a0 = *(float4*)(o_s + (gi - 1) * OS_ROW + c * 8 + 4);
            float r0 = 0.5f * (a1.x + a0.x);
            float r1 = 0.5f * (a1.y + a0.y);
            float r2 = 0.5f * (a1.z + a0.z);
            float r3 = 0.5f * (a1.w + a0.w);
            int ob = 4 * l1 - 2;
            *(float2*)(orow + ob)     = make_float2(r0, r1);
            *(float2*)(orow + ob + 2) = make_float2(r2, r3);
        } else {
            // boundary groups (l1 == 0 or l1 >= LOUT): per-q fallback
            #pragma unroll
            for (int k1 = 0; k1 < 4; k1++) {
                int q = 4 * l1 + k1;
                if (q < 2 || q > LEN + 1) continue;
                float v = 0.0f; int cnt = 0;
                if (l1 < LOUT) { v += o_s[gi * OS_ROW + c * 8 + k1];           cnt++; }
                if (l1 >= 1)   { v += o_s[(gi - 1) * OS_ROW + c * 8 + k1 + 4]; cnt++; }
                orow[q - 2] = (cnt == 2) ? v * 0.5f : v;
            }
        }
    }
}

extern "C" void kernel_launch(void* const* d_in, const int* in_sizes, int n_in,
                              void* d_out, int out_size)
{
    const float* x  = (const float*)d_in[0];
    const float* W1 = (const float*)d_in[1];
    const float* b1 = (const float*)d_in[2];
    const float* W2 = (const float*)d_in[3];
    const float* b2 = (const float*)d_in[4];
    float* out = (float*)d_out;

    weight_split_kernel<<<8, 256>>>(W1, W2);

    cudaFuncSetAttribute(fused_hmma_kernel,
                         cudaFuncAttributeMaxDynamicSharedMemorySize, SMEM_BYTES);
    dim3 grid(NBLK, 64);
    fused_hmma_kernel<<<grid, 256, SMEM_BYTES>>>(x, b1, b2, out);
}